// round 12
// baseline (speedup 1.0000x reference)
#include <cuda_runtime.h>
#include <cstdint>

// Problem constants (fixed by reference setup_inputs)
#define Bn 16
#define Cn 128
#define TA 2048
#define TB 1024
#define Rn TA   // reference timeline = modality A
#define GC 8    // channels per gather thread

// Output layout (float32, flattened in return order)
#define OFF_ALIGNED 0
#define OFF_MASK    8388608
#define OFF_IDX     8454144
#define OFF_RATIO   8519680

// Integer copy of the nearest-index table (avoids float->int cvt in gather)
__device__ int d_idxi[32 * 2048];

__device__ __forceinline__ void l2_prefetch(const void* p) {
    asm volatile("prefetch.global.L2 [%0];" :: "l"(p));
}

// -----------------------------------------------------------------------------
// Kernel 1 (fused): align + L2 warm-up for the gather's value reads.
// Grid: 256 blocks of 256 threads. blockIdx.x -> (mb = m*16+b, chunk of 256 refs).
//   m=0 fast path: idx[r] = r (self-match, distance 0) with exact
//     duplicate-timestamp walk-back; ok = masks_a[r] > 0.
//   m=1: order-preserving compaction + binary search (exact tie-breaks).
// Every block also prefetches a 1/256 slice of values_a/values_b into L2 so
// the gather kernel's compulsory DRAM reads overlap this kernel's latency.
// -----------------------------------------------------------------------------
__global__ __launch_bounds__(256)
void align_kernel(const float* __restrict__ ta, const float* __restrict__ ma,  // A t,m [B,TA]
                  const float* __restrict__ tb, const float* __restrict__ mb_, // B t,m [B,TB]
                  const float* __restrict__ va, const float* __restrict__ vb,  // values (prefetch only)
                  float* __restrict__ mask_out,  // [2,B,R]
                  float* __restrict__ idx_out,   // [2,B,R]
                  float* __restrict__ ratio)     // [2,B]
{
    __shared__ float s_t[2048];
    __shared__ int   s_i[2048];
    __shared__ int   wtot[8], woff[8];
    __shared__ int   s_nvA;

    const int t     = threadIdx.x;
    const int chunk = blockIdx.x & 7;
    const int mb    = blockIdx.x >> 3;    // 0..31
    const int m     = mb >> 4;
    const int b     = mb & 15;
    const int lane  = t & 31, wid = t >> 5;

    // ---- fire-and-forget L2 prefetch of values (1/256 slice per block) ----
    {
        // values_a: 16 MB = 131072 lines of 128B -> 512 lines/block
        const char* pa = (const char*)va + (size_t)blockIdx.x * (512 * 128);
        l2_prefetch(pa + (size_t)t * 128);
        l2_prefetch(pa + (size_t)(t + 256) * 128);
        // values_b: 8 MB -> 256 lines/block
        const char* pb = (const char*)vb + (size_t)blockIdx.x * (256 * 128);
        l2_prefetch(pb + (size_t)t * 128);
    }

    const float* ref_t = ta + (size_t)b * Rn;
    const float* ref_m = ma + (size_t)b * Rn;
    const int r = chunk * 256 + t;

    int   idx = -1;
    bool  ok;

    if (m == 0) {
        // ---- fast path: source == reference timeline ----
        const float rt = ref_t[r];
        ok = (ref_m[r] > 0.0f);
        if (ok) {
            // exact: smallest valid s with t[s] == t[r] (distance 0 run)
            int e0 = r;
            while (e0 > 0 && ref_t[e0 - 1] == rt) e0--;   // run start (O(1) exp.)
            int s = e0;
            while (ref_m[s] <= 0.0f) s++;                 // first valid, s <= r
            idx = s;
        }
    } else {
        // ---- general path: compact valid B sources, binary search ----
        const float* src_t = tb + (size_t)b * TB;
        const float* src_m = mb_ + (size_t)b * TB;
        const int per  = TB >> 8;            // 4
        const int base = t * per;

        float v_t[4], v_m[4];
        #pragma unroll
        for (int i = 0; i < 4; i++) { v_t[i] = src_t[base + i]; v_m[i] = src_m[base + i]; }
        int cnt = 0;
        #pragma unroll
        for (int i = 0; i < 4; i++) cnt += (v_m[i] > 0.0f) ? 1 : 0;

        int inc = cnt;
        #pragma unroll
        for (int off = 1; off < 32; off <<= 1) {
            int v = __shfl_up_sync(0xffffffffu, inc, off);
            if (lane >= off) inc += v;
        }
        if (lane == 31) wtot[wid] = inc;
        __syncthreads();
        if (t < 8) {
            int v = wtot[t];
            int s = v;
            #pragma unroll
            for (int off = 1; off < 8; off <<= 1) {
                int u = __shfl_up_sync(0x000000ffu, s, off);
                if (t >= off) s += u;
            }
            woff[t] = s - v;
        }
        __syncthreads();

        int pos = woff[wid] + inc - cnt;
        #pragma unroll
        for (int i = 0; i < 4; i++) {
            if (v_m[i] > 0.0f) { s_t[pos] = v_t[i]; s_i[pos] = base + i; pos++; }
        }
        const int nv = woff[7] + wtot[7];
        __syncthreads();

        const float rt = ref_t[r];
        ok = (ref_m[r] > 0.0f) && (nv > 0);
        if (ok) {
            int lo = 0, hi = nv;              // lower_bound: first s_t[pos] >= rt
            while (lo < hi) {
                int mid = (lo + hi) >> 1;
                if (s_t[mid] < rt) lo = mid + 1; else hi = mid;
            }
            int p;
            if (lo == 0) {
                p = 0;
            } else if (lo == nv || (rt - s_t[lo - 1]) <= (s_t[lo] - rt)) {
                float tl = s_t[lo - 1];
                p = lo - 1;
                while (p > 0 && s_t[p - 1] == tl) p--;    // first duplicate
            } else {
                p = lo;
            }
            idx = s_i[p];
        }
    }

    mask_out[(size_t)mb * Rn + r] = ok ? 1.0f : 0.0f;
    idx_out [(size_t)mb * Rn + r] = ok ? (float)idx : -1.0f;
    d_idxi  [(size_t)mb * Rn + r] = ok ? idx : -1;

    // ---- valid_ratio (chunk-0 blocks): ratio[m,b] = (any src ? nvA : 0)/2048 ----
    if (chunk == 0) {
        if (t == 0) s_nvA = 0;
        __syncthreads();
        const float* am = ma + (size_t)b * TA;
        int c2 = 0;
        #pragma unroll
        for (int i = 0; i < 8; i++)
            c2 += (am[t * 8 + i] > 0.0f) ? 1 : 0;
        #pragma unroll
        for (int off = 16; off > 0; off >>= 1)
            c2 += __shfl_down_sync(0xffffffffu, c2, off);
        if (lane == 0) atomicAdd(&s_nvA, c2);
        __syncthreads();
        if (t == 0) {
            int nvA = s_nvA;
            bool any_src;
            if (m == 0) {
                any_src = (nvA > 0);
            } else {
                // any valid B source for this b?
                const float* bm = mb_ + (size_t)b * TB;
                int c3 = 0;
                for (int i = 0; i < TB; i += 64)      // sparse probe? no — exact:
                    ;                                  // (replaced below)
                any_src = false;
                for (int i = 0; i < TB; i++)
                    if (bm[i] > 0.0f) { any_src = true; break; }
                (void)c3;
            }
            ratio[mb] = (any_src ? (float)nvA : 0.0f) * (1.0f / (float)Rn);
        }
    }
}

// -----------------------------------------------------------------------------
// Kernel 2: gather (best-measured R10 form). One thread serves GC=8 channels
// of one (m,b) with the same int4 index vector. grid: 1024 blocks of 256.
// -----------------------------------------------------------------------------
__global__ __launch_bounds__(256)
void gather_kernel(const float* __restrict__ vals_a,  // [B,C,TA]
                   const float* __restrict__ vals_b,  // [B,C,TB]
                   float* __restrict__ out)           // [2,B,C,R]
{
    const int bid   = blockIdx.x;
    const int rtile = bid & 1;
    const int ctile = (bid >> 1) & 15;
    const int mb    = bid >> 5;           // 0..31
    const int m     = mb >> 4;
    const int b     = mb & 15;
    const int S     = m ? TB : TA;
    const float* vals = m ? vals_b : vals_a;

    const int r4 = rtile * 256 + threadIdx.x;   // 0..511 (float4 granules of r)

    const int4 ix = __ldg((const int4*)(d_idxi + (size_t)mb * Rn) + r4);
    const bool vx = ix.x >= 0, vy = ix.y >= 0, vz = ix.z >= 0, vw = ix.w >= 0;

    const float* vbase = vals + ((size_t)b * Cn + ctile * GC) * S;
    float*       obase = out  + ((size_t)mb * Cn + ctile * GC) * Rn + r4 * 4;

    #pragma unroll
    for (int c = 0; c < GC; c++) {
        const float* vrow = vbase + (size_t)c * S;
        float4 o;
        o.x = vx ? __ldg(vrow + ix.x) : 0.0f;
        o.y = vy ? __ldg(vrow + ix.y) : 0.0f;
        o.z = vz ? __ldg(vrow + ix.z) : 0.0f;
        o.w = vw ? __ldg(vrow + ix.w) : 0.0f;
        *(float4*)(obase + (size_t)c * Rn) = o;
    }
}

extern "C" void kernel_launch(void* const* d_in, const int* in_sizes, int n_in,
                              void* d_out, int out_size)
{
    const float* values_a     = (const float*)d_in[0];
    const float* timestamps_a = (const float*)d_in[1];
    const float* masks_a      = (const float*)d_in[2];
    const float* values_b     = (const float*)d_in[3];
    const float* timestamps_b = (const float*)d_in[4];
    const float* masks_b      = (const float*)d_in[5];
    float* out = (float*)d_out;

    float* aligned = out + OFF_ALIGNED;
    float* maskout = out + OFF_MASK;   // [2,B,R]
    float* idxout  = out + OFF_IDX;    // [2,B,R]
    float* ratio   = out + OFF_RATIO;  // [2,B]

    // Phase 1: align + ratio + L2 warm-up of values (256 blocks)
    align_kernel<<<256, 256>>>(timestamps_a, masks_a, timestamps_b, masks_b,
                               values_a, values_b,
                               maskout, idxout, ratio);

    // Phase 2: gather -> aligned [2,B,C,R] (reads now mostly L2-warm)
    gather_kernel<<<1024, 256>>>(values_a, values_b, aligned);

    (void)in_sizes; (void)n_in; (void)out_size;
}

// round 13
// speedup vs baseline: 1.0787x; 1.0787x over previous
#include <cuda_runtime.h>
#include <cstdint>

// Problem constants (fixed by reference setup_inputs)
#define Bn 16
#define Cn 128
#define TA 2048
#define TB 1024
#define Rn TA   // reference timeline = modality A
#define GC 8    // channels per gather thread

// Output layout (float32, flattened in return order)
#define OFF_ALIGNED 0
#define OFF_MASK    8388608
#define OFF_IDX     8454144
#define OFF_RATIO   8519680

// Integer copy of the nearest-index table (avoids float->int cvt in gather)
__device__ int d_idxi[32 * 2048];

// -----------------------------------------------------------------------------
// Kernel 1 (fused): per-block redundant compaction + binary search + ratio.
// (R10 version — best measured: ~2.9us.)
// Grid: 256 blocks of 256 threads. blockIdx.x -> (mb = m*16+b, chunk of 256 refs).
// -----------------------------------------------------------------------------
__global__ __launch_bounds__(256)
void align_kernel(const float* __restrict__ ta, const float* __restrict__ ma,  // A t,m [B,TA]
                  const float* __restrict__ tb, const float* __restrict__ mb_, // B t,m [B,TB]
                  float* __restrict__ mask_out,  // [2,B,R]
                  float* __restrict__ idx_out,   // [2,B,R]
                  float* __restrict__ ratio)     // [2,B]
{
    __shared__ float s_t[2048];
    __shared__ int   s_i[2048];
    __shared__ int   wtot[8], woff[8];
    __shared__ int   s_nvA;

    const int t     = threadIdx.x;
    const int chunk = blockIdx.x & 7;
    const int mb    = blockIdx.x >> 3;    // 0..31
    const int m     = mb >> 4;
    const int b     = mb & 15;
    const int S     = m ? TB : TA;

    const float* src_t = (m ? tb : ta) + (size_t)b * S;
    const float* src_m = (m ? mb_ : ma) + (size_t)b * S;

    // ---- order-preserving compaction into smem ----
    const int per  = S >> 8;              // 8 (A) or 4 (B)
    const int base = t * per;
    const int lane = t & 31, wid = t >> 5;

    float v_t[8];
    float v_m[8];
    #pragma unroll
    for (int i = 0; i < 8; i++) {
        if (i < per) {
            v_t[i] = src_t[base + i];
            v_m[i] = src_m[base + i];
        }
    }
    int cnt = 0;
    #pragma unroll
    for (int i = 0; i < 8; i++)
        if (i < per) cnt += (v_m[i] > 0.0f) ? 1 : 0;

    // block scan: warp shuffle scan + warp-total scan
    int inc = cnt;
    #pragma unroll
    for (int off = 1; off < 32; off <<= 1) {
        int v = __shfl_up_sync(0xffffffffu, inc, off);
        if (lane >= off) inc += v;
    }
    if (lane == 31) wtot[wid] = inc;
    __syncthreads();
    if (t < 8) {
        int v = wtot[t];
        int s = v;
        #pragma unroll
        for (int off = 1; off < 8; off <<= 1) {
            int u = __shfl_up_sync(0x000000ffu, s, off);
            if (t >= off) s += u;
        }
        woff[t] = s - v;                  // exclusive warp offset
    }
    __syncthreads();

    int pos = woff[wid] + inc - cnt;      // exclusive prefix for this thread
    #pragma unroll
    for (int i = 0; i < 8; i++) {
        if (i < per && v_m[i] > 0.0f) {
            s_t[pos] = v_t[i];
            s_i[pos] = base + i;
            pos++;
        }
    }
    const int nv = woff[7] + wtot[7];     // total valid count
    __syncthreads();

    // ---- binary search: 256 refs per block, one per thread ----
    const int r = chunk * 256 + t;
    const float rt = ta[(size_t)b * Rn + r];
    const bool ok = (ma[(size_t)b * Rn + r] > 0.0f) && (nv > 0);

    int idx = -1;
    if (ok) {
        int lo = 0, hi = nv;              // lower_bound: first s_t[pos] >= rt
        while (lo < hi) {
            int mid = (lo + hi) >> 1;
            if (s_t[mid] < rt) lo = mid + 1; else hi = mid;
        }
        int p;
        if (lo == 0) {
            p = 0;                                      // only right candidate
        } else if (lo == nv || (rt - s_t[lo - 1]) <= (s_t[lo] - rt)) {
            float tl = s_t[lo - 1];
            p = lo - 1;
            while (p > 0 && s_t[p - 1] == tl) p--;      // first duplicate
        } else {
            p = lo;                                     // lo is first occurrence
        }
        idx = s_i[p];
    }
    mask_out[(size_t)mb * Rn + r] = ok ? 1.0f : 0.0f;
    idx_out [(size_t)mb * Rn + r] = ok ? (float)idx : -1.0f;
    d_idxi  [(size_t)mb * Rn + r] = ok ? idx : -1;

    // ---- valid_ratio (chunk-0 blocks only) ----
    if (chunk == 0) {
        // ratio[m,b] = (nv>0 ? nvA : 0) / 2048, nvA = #valid in masks_a[b].
        if (m == 0) {
            if (t == 0)
                ratio[mb] = (nv > 0 ? (float)nv : 0.0f) * (1.0f / (float)Rn);
        } else {
            if (t == 0) s_nvA = 0;
            __syncthreads();
            const float* am = ma + (size_t)b * TA;
            int c2 = 0;
            #pragma unroll
            for (int i = 0; i < 8; i++)
                c2 += (am[t * 8 + i] > 0.0f) ? 1 : 0;
            #pragma unroll
            for (int off = 16; off > 0; off >>= 1)
                c2 += __shfl_down_sync(0xffffffffu, c2, off);
            if (lane == 0) atomicAdd(&s_nvA, c2);
            __syncthreads();
            if (t == 0)
                ratio[mb] = (nv > 0 ? (float)s_nvA : 0.0f) * (1.0f / (float)Rn);
        }
    }
}

// -----------------------------------------------------------------------------
// Kernel 2: gather, m-specialized.
//   m=0: idx[r] == r whenever valid (self-alignment), except measure-zero
//        duplicate-timestamp cases. Vectorized LDG.128 copy with an exact
//        per-component fallback (predicated scalar load when ix != r).
//   m=1: scalar-gather path (best-measured R10 form).
// One thread serves GC=8 channels with a single int4 index vector.
// grid: mb(32) x ctile(16) x rtile(2) = 1024 blocks of 256 threads.
// -----------------------------------------------------------------------------
__global__ __launch_bounds__(256)
void gather_kernel(const float* __restrict__ vals_a,  // [B,C,TA]
                   const float* __restrict__ vals_b,  // [B,C,TB]
                   float* __restrict__ out)           // [2,B,C,R]
{
    const int bid   = blockIdx.x;
    const int rtile = bid & 1;
    const int ctile = (bid >> 1) & 15;
    const int mb    = bid >> 5;           // 0..31
    const int m     = mb >> 4;
    const int b     = mb & 15;

    const int r4 = rtile * 256 + threadIdx.x;   // 0..511 (float4 granules of r)

    const int4 ix = __ldg((const int4*)(d_idxi + (size_t)mb * Rn) + r4);
    const bool vx = ix.x >= 0, vy = ix.y >= 0, vz = ix.z >= 0, vw = ix.w >= 0;

    float* obase = out + ((size_t)mb * Cn + ctile * GC) * Rn + r4 * 4;

    if (m == 0) {
        // ---- vectorized masked copy with exact rare fallback ----
        const float* vbase = vals_a + ((size_t)b * Cn + ctile * GC) * TA;
        const int rb = r4 * 4;
        #pragma unroll
        for (int c = 0; c < GC; c++) {
            const float* vrow = vbase + (size_t)c * TA;
            float4 v = __ldg((const float4*)vrow + r4);   // vrow[rb .. rb+3]
            // exact: fall back to scalar gather iff idx != r (duplicates)
            if (vx && ix.x != rb    ) v.x = __ldg(vrow + ix.x);
            if (vy && ix.y != rb + 1) v.y = __ldg(vrow + ix.y);
            if (vz && ix.z != rb + 2) v.z = __ldg(vrow + ix.z);
            if (vw && ix.w != rb + 3) v.w = __ldg(vrow + ix.w);
            float4 o;
            o.x = vx ? v.x : 0.0f;
            o.y = vy ? v.y : 0.0f;
            o.z = vz ? v.z : 0.0f;
            o.w = vw ? v.w : 0.0f;
            *(float4*)(obase + (size_t)c * Rn) = o;
        }
    } else {
        // ---- scalar gather (B timeline, idx step ~0.5) ----
        const float* vbase = vals_b + ((size_t)b * Cn + ctile * GC) * TB;
        #pragma unroll
        for (int c = 0; c < GC; c++) {
            const float* vrow = vbase + (size_t)c * TB;
            float4 o;
            o.x = vx ? __ldg(vrow + ix.x) : 0.0f;
            o.y = vy ? __ldg(vrow + ix.y) : 0.0f;
            o.z = vz ? __ldg(vrow + ix.z) : 0.0f;
            o.w = vw ? __ldg(vrow + ix.w) : 0.0f;
            *(float4*)(obase + (size_t)c * Rn) = o;
        }
    }
}

extern "C" void kernel_launch(void* const* d_in, const int* in_sizes, int n_in,
                              void* d_out, int out_size)
{
    const float* values_a     = (const float*)d_in[0];
    const float* timestamps_a = (const float*)d_in[1];
    const float* masks_a      = (const float*)d_in[2];
    const float* values_b     = (const float*)d_in[3];
    const float* timestamps_b = (const float*)d_in[4];
    const float* masks_b      = (const float*)d_in[5];
    float* out = (float*)d_out;

    float* aligned = out + OFF_ALIGNED;
    float* maskout = out + OFF_MASK;   // [2,B,R]
    float* idxout  = out + OFF_IDX;    // [2,B,R]
    float* ratio   = out + OFF_RATIO;  // [2,B]

    // Phase 1: fused compaction + search + ratio (256 blocks)
    align_kernel<<<256, 256>>>(timestamps_a, masks_a, timestamps_b, masks_b,
                               maskout, idxout, ratio);

    // Phase 2: gather -> aligned [2,B,C,R]
    gather_kernel<<<1024, 256>>>(values_a, values_b, aligned);

    (void)in_sizes; (void)n_in; (void)out_size;
}